// round 1
// baseline (speedup 1.0000x reference)
#include <cuda_runtime.h>

#define NODES 100000
#define EDGES 1600000
#define F 256
#define F2 512

// ---------------- scratch (device globals: no allocation allowed) ------------
__device__ float g_hw[NODES * F];       // (h@W)*norm  — 102.4 MB
__device__ float g_w2[F * F2];          // combined weight [k][0:256]=W, [256:512]=res_w^T
__device__ int   g_deg[NODES];
__device__ int   g_off[NODES];
__device__ int   g_cur[NODES];
__device__ int   g_csrc[EDGES];
__device__ int   g_bsum[128];

// ---------------- CSR build --------------------------------------------------
__global__ void k_zero_deg() {
    int i = blockIdx.x * blockDim.x + threadIdx.x;
    if (i < NODES) g_deg[i] = 0;
}

__global__ void k_count(const int* __restrict__ dst) {
    int e = blockIdx.x * blockDim.x + threadIdx.x;
    if (e < EDGES) atomicAdd(&g_deg[dst[e]], 1);
}

__global__ void k_scan1() {
    __shared__ int sm[1024];
    int i = blockIdx.x * 1024 + threadIdx.x;
    int v = (i < NODES) ? g_deg[i] : 0;
    sm[threadIdx.x] = v;
    __syncthreads();
    for (int s = 1; s < 1024; s <<= 1) {
        int t = (threadIdx.x >= s) ? sm[threadIdx.x - s] : 0;
        __syncthreads();
        sm[threadIdx.x] += t;
        __syncthreads();
    }
    if (i < NODES) g_off[i] = sm[threadIdx.x] - v;   // exclusive within block
    if (threadIdx.x == 1023) g_bsum[blockIdx.x] = sm[1023];
}

__global__ void k_scan2(int nblocks) {
    if (threadIdx.x == 0 && blockIdx.x == 0) {
        int run = 0;
        for (int b = 0; b < nblocks; b++) { int t = g_bsum[b]; g_bsum[b] = run; run += t; }
    }
}

__global__ void k_scan3() {
    int i = blockIdx.x * blockDim.x + threadIdx.x;
    if (i < NODES) {
        int o = g_off[i] + g_bsum[i >> 10];
        g_off[i] = o;
        g_cur[i] = o;
    }
}

__global__ void k_scatter(const int* __restrict__ src, const int* __restrict__ dst) {
    int e = blockIdx.x * blockDim.x + threadIdx.x;
    if (e < EDGES) {
        int p = atomicAdd(&g_cur[dst[e]], 1);
        g_csrc[p] = src[e];
    }
}

// ---------------- combined weight build --------------------------------------
__global__ void k_build_w2(const float* __restrict__ weight, const float* __restrict__ res_w) {
    int i = blockIdx.x * blockDim.x + threadIdx.x;   // over 256*512
    if (i < F * F2) {
        int k = i / F2, j = i % F2;
        g_w2[i] = (j < F) ? weight[k * F + j] : res_w[(j - F) * F + k];
    }
}

// ---------------- dual GEMM: hw = (h@W)*norm ; res = h@res_w^T + res_b -------
#define BM 128
#define BN 64
#define BK 16
#define TM 8
#define TN 4

__global__ void __launch_bounds__(256) k_gemm(
    const float* __restrict__ h, const float* __restrict__ norm,
    const float* __restrict__ res_b, float* __restrict__ out)
{
    __shared__ float As[BK][BM + 4];
    __shared__ float Bs[BK][BN];

    int m0 = blockIdx.x * BM;
    int j0 = blockIdx.y * BN;
    int tid = threadIdx.x;
    int ty = tid >> 4;   // 0..15
    int tx = tid & 15;   // 0..15

    float acc[TM][TN];
#pragma unroll
    for (int i = 0; i < TM; i++)
#pragma unroll
        for (int j = 0; j < TN; j++) acc[i][j] = 0.f;

    for (int k0 = 0; k0 < F; k0 += BK) {
        // A tile: 128 rows x 16 k = 512 float4; 2 per thread. Store transposed.
#pragma unroll
        for (int l = 0; l < 2; l++) {
            int q  = tid + l * 256;
            int ar = q >> 2;           // 0..127
            int ac = (q & 3) << 2;     // 0,4,8,12
            int grow = m0 + ar;
            float4 v = make_float4(0.f, 0.f, 0.f, 0.f);
            if (grow < NODES) v = *(const float4*)&h[grow * F + k0 + ac];
            As[ac + 0][ar] = v.x;
            As[ac + 1][ar] = v.y;
            As[ac + 2][ar] = v.z;
            As[ac + 3][ar] = v.w;
        }
        // B tile: 16 k x 64 cols = 256 float4; 1 per thread.
        {
            int br = tid >> 4;           // 0..15
            int bc = (tid & 15) << 2;    // 0..60
            float4 v = *(const float4*)&g_w2[(k0 + br) * F2 + j0 + bc];
            *(float4*)&Bs[br][bc] = v;
        }
        __syncthreads();

#pragma unroll
        for (int kk = 0; kk < BK; kk++) {
            float a[TM], b[TN];
#pragma unroll
            for (int i = 0; i < TM; i++) a[i] = As[kk][ty * TM + i];
#pragma unroll
            for (int j = 0; j < TN; j++) b[j] = Bs[kk][tx * TN + j];
#pragma unroll
            for (int i = 0; i < TM; i++)
#pragma unroll
                for (int j = 0; j < TN; j++) acc[i][j] += a[i] * b[j];
        }
        __syncthreads();
    }

#pragma unroll
    for (int i = 0; i < TM; i++) {
        int row = m0 + ty * TM + i;
        if (row < NODES) {
            float nr = norm[row];
#pragma unroll
            for (int j = 0; j < TN; j++) {
                int col = j0 + tx * TN + j;
                if (col < F) {
                    g_hw[row * F + col] = acc[i][j] * nr;
                } else {
                    out[row * F + (col - F)] = acc[i][j] + res_b[col - F];
                }
            }
        }
    }
}

// ---------------- aggregation + fused epilogue -------------------------------
// One warp per node. Lane owns 8 contiguous features (2x float4).
// out = relu(segsum(hw[src]) * norm + bias + res), res already in `out`.
__global__ void __launch_bounds__(256) k_agg(
    const float* __restrict__ norm, const float* __restrict__ bias,
    float* __restrict__ out)
{
    int gw   = (blockIdx.x * blockDim.x + threadIdx.x) >> 5;
    int lane = threadIdx.x & 31;
    if (gw >= NODES) return;

    int start = g_off[gw];
    int deg   = g_deg[gw];

    float4 a0 = make_float4(0.f, 0.f, 0.f, 0.f);
    float4 a1 = make_float4(0.f, 0.f, 0.f, 0.f);

    int fo = lane * 8;
    for (int i = 0; i < deg; i++) {
        int s = g_csrc[start + i];                    // broadcast load
        const float4* p = (const float4*)&g_hw[s * F + fo];
        float4 v0 = p[0];
        float4 v1 = p[1];
        a0.x += v0.x; a0.y += v0.y; a0.z += v0.z; a0.w += v0.w;
        a1.x += v1.x; a1.y += v1.y; a1.z += v1.z; a1.w += v1.w;
    }

    float nr = norm[gw];
    float4 b0 = *(const float4*)&bias[fo];
    float4 b1 = *(const float4*)&bias[fo + 4];
    float4 r0 = *(const float4*)&out[gw * F + fo];
    float4 r1 = *(const float4*)&out[gw * F + fo + 4];

    float4 o0, o1;
    o0.x = fmaxf(a0.x * nr + b0.x + r0.x, 0.f);
    o0.y = fmaxf(a0.y * nr + b0.y + r0.y, 0.f);
    o0.z = fmaxf(a0.z * nr + b0.z + r0.z, 0.f);
    o0.w = fmaxf(a0.w * nr + b0.w + r0.w, 0.f);
    o1.x = fmaxf(a1.x * nr + b1.x + r1.x, 0.f);
    o1.y = fmaxf(a1.y * nr + b1.y + r1.y, 0.f);
    o1.z = fmaxf(a1.z * nr + b1.z + r1.z, 0.f);
    o1.w = fmaxf(a1.w * nr + b1.w + r1.w, 0.f);

    *(float4*)&out[gw * F + fo]     = o0;
    *(float4*)&out[gw * F + fo + 4] = o1;
}

// ---------------- launch ------------------------------------------------------
extern "C" void kernel_launch(void* const* d_in, const int* in_sizes, int n_in,
                              void* d_out, int out_size)
{
    const float* h      = (const float*)d_in[0];
    const float* norm   = (const float*)d_in[1];
    const int*   src    = (const int*)d_in[2];
    const int*   dst    = (const int*)d_in[3];
    const float* weight = (const float*)d_in[4];
    const float* bias   = (const float*)d_in[5];
    const float* res_w  = (const float*)d_in[6];
    const float* res_b  = (const float*)d_in[7];
    float* out = (float*)d_out;

    (void)in_sizes; (void)n_in; (void)out_size;

    // CSR build
    k_zero_deg<<<(NODES + 255) / 256, 256>>>();
    k_count<<<(EDGES + 255) / 256, 256>>>(dst);
    int nscan = (NODES + 1023) / 1024;               // 98
    k_scan1<<<nscan, 1024>>>();
    k_scan2<<<1, 32>>>(nscan);
    k_scan3<<<(NODES + 255) / 256, 256>>>();
    k_scatter<<<(EDGES + 255) / 256, 256>>>(src, dst);

    // combined weight
    k_build_w2<<<(F * F2 + 255) / 256, 256>>>(weight, res_w);

    // dual GEMM: hw -> g_hw, res -> out
    dim3 ggrid((NODES + BM - 1) / BM, F2 / BN);      // 782 x 8
    k_gemm<<<ggrid, 256>>>(h, norm, res_b, out);

    // aggregation + epilogue
    int nwarp_blocks = (NODES * 32 + 255) / 256;     // 12500
    k_agg<<<nwarp_blocks, 256>>>(norm, bias, out);
}

// round 3
// speedup vs baseline: 1.3617x; 1.3617x over previous
#include <cuda_runtime.h>
#include <cuda_bf16.h>
#include <cstdint>

#define NODES 100000
#define NODES_P 100096            // 782 * 128
#define EDGES 1600000
#define F 256
#define F2 512
#define KP 768                    // K' = 3*F  ([Ahi|Alo|Ahi] x [Bhi;Bhi;Blo])

// ---------------- scratch (device globals) -----------------------------------
__device__ __nv_bfloat16 g_a2[(size_t)NODES_P * KP];   // ~154 MB
__device__ __nv_bfloat16 g_b2[F2 * KP];
__device__ float g_hw[(size_t)NODES * F];              // (h@W)*norm
__device__ int   g_deg[NODES];
__device__ int   g_off[NODES];
__device__ int   g_cur[NODES];
__device__ int   g_csrc[EDGES];
__device__ int   g_bsum[128];

// ---------------- CSR build --------------------------------------------------
__global__ void k_zero_deg() {
    int i = blockIdx.x * blockDim.x + threadIdx.x;
    if (i < NODES) g_deg[i] = 0;
}

__global__ void k_count(const int* __restrict__ dst) {
    int e = blockIdx.x * blockDim.x + threadIdx.x;
    if (e < EDGES) atomicAdd(&g_deg[dst[e]], 1);
}

__global__ void k_scan1() {
    __shared__ int sm[1024];
    int i = blockIdx.x * 1024 + threadIdx.x;
    int v = (i < NODES) ? g_deg[i] : 0;
    sm[threadIdx.x] = v;
    __syncthreads();
    for (int s = 1; s < 1024; s <<= 1) {
        int t = (threadIdx.x >= s) ? sm[threadIdx.x - s] : 0;
        __syncthreads();
        sm[threadIdx.x] += t;
        __syncthreads();
    }
    if (i < NODES) g_off[i] = sm[threadIdx.x] - v;
    if (threadIdx.x == 1023) g_bsum[blockIdx.x] = sm[1023];
}

__global__ void k_scan2(int nblocks) {
    if (threadIdx.x == 0 && blockIdx.x == 0) {
        int run = 0;
        for (int b = 0; b < nblocks; b++) { int t = g_bsum[b]; g_bsum[b] = run; run += t; }
    }
}

__global__ void k_scan3() {
    int i = blockIdx.x * blockDim.x + threadIdx.x;
    if (i < NODES) {
        int o = g_off[i] + g_bsum[i >> 10];
        g_off[i] = o;
        g_cur[i] = o;
    }
}

__global__ void k_scatter(const int* __restrict__ src, const int* __restrict__ dst) {
    int e = blockIdx.x * blockDim.x + threadIdx.x;
    if (e < EDGES) {
        int p = atomicAdd(&g_cur[dst[e]], 1);
        g_csrc[p] = src[e];
    }
}

// ---------------- fp32 -> bf16 hi/lo operand build ---------------------------
__global__ void k_conv_h(const float* __restrict__ h) {
    int i = blockIdx.x * blockDim.x + threadIdx.x;   // over NODES_P*64 float4s
    if (i >= NODES_P * (F / 4)) return;
    int row = i >> 6;
    int c4  = (i & 63) * 4;
    float4 v = make_float4(0.f, 0.f, 0.f, 0.f);
    if (row < NODES) v = *(const float4*)&h[(size_t)row * F + c4];
    __nv_bfloat16 hi[4], lo[4];
    float x[4] = {v.x, v.y, v.z, v.w};
#pragma unroll
    for (int j = 0; j < 4; j++) {
        hi[j] = __float2bfloat16_rn(x[j]);
        lo[j] = __float2bfloat16_rn(x[j] - __bfloat162float(hi[j]));
    }
    size_t o = (size_t)row * KP;
    *(uint2*)&g_a2[o + c4]       = *(uint2*)hi;
    *(uint2*)&g_a2[o + F + c4]   = *(uint2*)lo;
    *(uint2*)&g_a2[o + 2*F + c4] = *(uint2*)hi;
}

// B' [n][k'] K-major: n<256 -> weight[k][n]; n>=256 -> res_w[n-256][k]
__global__ void k_conv_b(const float* __restrict__ weight, const float* __restrict__ res_w) {
    int i = blockIdx.x * blockDim.x + threadIdx.x;   // over F2*F
    if (i >= F2 * F) return;
    int n = i / F, k = i % F;
    float x = (n < F) ? weight[k * F + n] : res_w[(n - F) * F + k];
    __nv_bfloat16 hi = __float2bfloat16_rn(x);
    __nv_bfloat16 lo = __float2bfloat16_rn(x - __bfloat162float(hi));
    size_t o = (size_t)n * KP;
    g_b2[o + k]       = hi;
    g_b2[o + F + k]   = hi;
    g_b2[o + 2*F + k] = lo;
}

// ---------------- HMMA GEMM (mma.sync m16n8k16 bf16, portable PTX) -----------
#define BM 128
#define BN 128
#define BK 64
#define NKC (KP / BK)            // 12
#define SMEM_DYN (4 * 16384)     // double-buffered A(16K)+B(16K)

__device__ __forceinline__ uint32_t smem_u32(const void* p) {
    uint32_t a;
    asm("{ .reg .u64 t; cvta.to.shared.u64 t, %1; cvt.u32.u64 %0, t; }" : "=r"(a) : "l"(p));
    return a;
}

// 128B-row swizzle: 16B chunk cg within row r goes to cg ^ (r&7)
__device__ __forceinline__ uint32_t sw(uint32_t r, uint32_t cg) {
    return r * 128u + ((cg ^ (r & 7u)) << 4);
}

__device__ __forceinline__ void cp16(uint32_t s, const void* g) {
    asm volatile("cp.async.cg.shared.global [%0], [%1], 16;" :: "r"(s), "l"(g));
}

__device__ __forceinline__ void ldsm_x4(uint32_t* r, uint32_t addr) {
    asm volatile("ldmatrix.sync.aligned.m8n8.x4.shared.b16 {%0,%1,%2,%3}, [%4];"
                 : "=r"(r[0]), "=r"(r[1]), "=r"(r[2]), "=r"(r[3]) : "r"(addr));
}

__device__ __forceinline__ void mma_bf16(float* d, const uint32_t* a, uint32_t b0, uint32_t b1) {
    asm volatile(
        "mma.sync.aligned.m16n8k16.row.col.f32.bf16.bf16.f32 "
        "{%0,%1,%2,%3}, {%4,%5,%6,%7}, {%8,%9}, {%0,%1,%2,%3};"
        : "+f"(d[0]), "+f"(d[1]), "+f"(d[2]), "+f"(d[3])
        : "r"(a[0]), "r"(a[1]), "r"(a[2]), "r"(a[3]), "r"(b0), "r"(b1));
}

__global__ void __launch_bounds__(256, 2) k_gemm_mma(
    const float* __restrict__ norm, const float* __restrict__ res_b,
    float* __restrict__ out)
{
    extern __shared__ char smem[];
    const int tid  = threadIdx.x;
    const int wid  = tid >> 5;
    const int lane = tid & 31;
    const int wm = wid & 1;          // 2 warps along M
    const int wn = wid >> 1;         // 4 warps along N
    const size_t m0 = (size_t)blockIdx.y * BM;
    const int n0 = blockIdx.x * BN;

    const uint32_t sbase = smem_u32(smem);

    float acc[4][4][4];
#pragma unroll
    for (int i = 0; i < 4; i++)
#pragma unroll
        for (int j = 0; j < 4; j++)
#pragma unroll
            for (int q = 0; q < 4; q++) acc[i][j][q] = 0.f;

    const __nv_bfloat16* gA = g_a2 + m0 * KP;
    const __nv_bfloat16* gB = g_b2 + (size_t)n0 * KP;

    const int lr = tid >> 3;   // 0..31
    const int lc = tid & 7;    // 16B chunk 0..7

    // ---- prologue: chunk 0 into buffer 0 ----
    {
        uint32_t sA = sbase, sB = sbase + 16384;
        const __nv_bfloat16* pa = gA + lc * 8;
        const __nv_bfloat16* pb = gB + lc * 8;
#pragma unroll
        for (int i = 0; i < 4; i++) {
            int r = lr + i * 32;
            cp16(sA + sw(r, lc), pa + (size_t)r * KP);
            cp16(sB + sw(r, lc), pb + (size_t)r * KP);
        }
        asm volatile("cp.async.commit_group;");
    }

    for (int kc = 0; kc < NKC; kc++) {
        int b = kc & 1;
        if (kc + 1 < NKC) {
            uint32_t sA = sbase + (b ^ 1) * 32768, sB = sA + 16384;
            const __nv_bfloat16* pa = gA + (kc + 1) * BK + lc * 8;
            const __nv_bfloat16* pb = gB + (kc + 1) * BK + lc * 8;
#pragma unroll
            for (int i = 0; i < 4; i++) {
                int r = lr + i * 32;
                cp16(sA + sw(r, lc), pa + (size_t)r * KP);
                cp16(sB + sw(r, lc), pb + (size_t)r * KP);
            }
            asm volatile("cp.async.commit_group;");
            asm volatile("cp.async.wait_group 1;");
        } else {
            asm volatile("cp.async.wait_group 0;");
        }
        __syncthreads();

        uint32_t sA = sbase + b * 32768, sB = sA + 16384;
#pragma unroll
        for (int ks = 0; ks < 4; ks++) {
            uint32_t a[4][4], bb[2][4];
            {
                int row = wm * 64 + (lane & 7) + ((lane >> 3) & 1) * 8;
                int cg  = ks * 2 + (lane >> 4);
#pragma unroll
                for (int i = 0; i < 4; i++)
                    ldsm_x4(a[i], sA + sw(row + i * 16, cg));
            }
            {
                int row = wn * 32 + (lane & 7) + ((lane >> 4) & 1) * 8;
                int cg  = ks * 2 + ((lane >> 3) & 1);
#pragma unroll
                for (int j = 0; j < 2; j++)
                    ldsm_x4(bb[j], sB + sw(row + j * 16, cg));
            }
#pragma unroll
            for (int i = 0; i < 4; i++)
#pragma unroll
                for (int j = 0; j < 4; j++)
                    mma_bf16(acc[i][j], a[i], bb[j >> 1][(j & 1) * 2], bb[j >> 1][(j & 1) * 2 + 1]);
        }
        __syncthreads();
    }

    // ---- fused epilogue ----
    const int tq = lane >> 2;   // row within m16 tile
    const int tr = lane & 3;    // col pair within n8 tile
#pragma unroll
    for (int i = 0; i < 4; i++) {
        size_t row = m0 + wm * 64 + i * 16 + tq;
        bool v0 = row < NODES;
        bool v1 = (row + 8) < NODES;
        float nr0 = v0 ? norm[row] : 0.f;
        float nr1 = v1 ? norm[row + 8] : 0.f;
#pragma unroll
        for (int j = 0; j < 4; j++) {
            int cn = n0 + wn * 32 + j * 8 + tr * 2;
            if (cn < F) {
                if (v0) *(float2*)&g_hw[row * F + cn] =
                    make_float2(acc[i][j][0] * nr0, acc[i][j][1] * nr0);
                if (v1) *(float2*)&g_hw[(row + 8) * F + cn] =
                    make_float2(acc[i][j][2] * nr1, acc[i][j][3] * nr1);
            } else {
                int oc = cn - F;
                float2 rb = *(const float2*)&res_b[oc];
                if (v0) *(float2*)&out[row * F + oc] =
                    make_float2(acc[i][j][0] + rb.x, acc[i][j][1] + rb.y);
                if (v1) *(float2*)&out[(row + 8) * F + oc] =
                    make_float2(acc[i][j][2] + rb.x, acc[i][j][3] + rb.y);
            }
        }
    }
}

// ---------------- aggregation + fused epilogue -------------------------------
__global__ void __launch_bounds__(256) k_agg(
    const float* __restrict__ norm, const float* __restrict__ bias,
    float* __restrict__ out)
{
    int gw   = (blockIdx.x * blockDim.x + threadIdx.x) >> 5;
    int lane = threadIdx.x & 31;
    if (gw >= NODES) return;

    int start = g_off[gw];
    int deg   = g_deg[gw];

    float4 a0 = make_float4(0.f, 0.f, 0.f, 0.f);
    float4 a1 = make_float4(0.f, 0.f, 0.f, 0.f);

    int fo = lane * 8;
    for (int i = 0; i < deg; i++) {
        int s = g_csrc[start + i];
        const float4* p = (const float4*)&g_hw[(size_t)s * F + fo];
        float4 v0 = p[0];
        float4 v1 = p[1];
        a0.x += v0.x; a0.y += v0.y; a0.z += v0.z; a0.w += v0.w;
        a1.x += v1.x; a1.y += v1.y; a1.z += v1.z; a1.w += v1.w;
    }

    float nr = norm[gw];
    float4 b0 = *(const float4*)&bias[fo];
    float4 b1 = *(const float4*)&bias[fo + 4];
    float4 r0 = *(const float4*)&out[(size_t)gw * F + fo];
    float4 r1 = *(const float4*)&out[(size_t)gw * F + fo + 4];

    float4 o0, o1;
    o0.x = fmaxf(a0.x * nr + b0.x + r0.x, 0.f);
    o0.y = fmaxf(a0.y * nr + b0.y + r0.y, 0.f);
    o0.z = fmaxf(a0.z * nr + b0.z + r0.z, 0.f);
    o0.w = fmaxf(a0.w * nr + b0.w + r0.w, 0.f);
    o1.x = fmaxf(a1.x * nr + b1.x + r1.x, 0.f);
    o1.y = fmaxf(a1.y * nr + b1.y + r1.y, 0.f);
    o1.z = fmaxf(a1.z * nr + b1.z + r1.z, 0.f);
    o1.w = fmaxf(a1.w * nr + b1.w + r1.w, 0.f);

    *(float4*)&out[(size_t)gw * F + fo]     = o0;
    *(float4*)&out[(size_t)gw * F + fo + 4] = o1;
}

// ---------------- launch ------------------------------------------------------
extern "C" void kernel_launch(void* const* d_in, const int* in_sizes, int n_in,
                              void* d_out, int out_size)
{
    const float* h      = (const float*)d_in[0];
    const float* norm   = (const float*)d_in[1];
    const int*   src    = (const int*)d_in[2];
    const int*   dst    = (const int*)d_in[3];
    const float* weight = (const float*)d_in[4];
    const float* bias   = (const float*)d_in[5];
    const float* res_w  = (const float*)d_in[6];
    const float* res_b  = (const float*)d_in[7];
    float* out = (float*)d_out;

    (void)in_sizes; (void)n_in; (void)out_size;

    cudaFuncSetAttribute(k_gemm_mma, cudaFuncAttributeMaxDynamicSharedMemorySize, SMEM_DYN);

    // CSR build
    k_zero_deg<<<(NODES + 255) / 256, 256>>>();
    k_count<<<(EDGES + 255) / 256, 256>>>(dst);
    int nscan = (NODES + 1023) / 1024;
    k_scan1<<<nscan, 1024>>>();
    k_scan2<<<1, 32>>>(nscan);
    k_scan3<<<(NODES + 255) / 256, 256>>>();
    k_scatter<<<(EDGES + 255) / 256, 256>>>(src, dst);

    // bf16 hi/lo operand build
    k_conv_h<<<(NODES_P * (F / 4) + 255) / 256, 256>>>(h);
    k_conv_b<<<(F2 * F + 255) / 256, 256>>>(weight, res_w);

    // HMMA dual GEMM: hw -> g_hw, res -> out
    dim3 ggrid(F2 / BN, NODES_P / BM);   // 4 x 782
    k_gemm_mma<<<ggrid, 256, SMEM_DYN>>>(norm, res_b, out);

    // aggregation + epilogue
    int nwarp_blocks = (NODES * 32 + 255) / 256;
    k_agg<<<nwarp_blocks, 256>>>(norm, bias, out);
}

// round 4
// speedup vs baseline: 1.9569x; 1.4371x over previous
#include <cuda_runtime.h>
#include <cuda_bf16.h>
#include <cstdint>

#define NODES 100000
#define NODES_P 100096            // 782 * 128
#define EDGES 1600000
#define F 256
#define F2 512
#define KPA 512                   // A' = [Ahi | Alo]
#define KPB 768                   // B' = [Bhi ; Bhi ; Blo]

// ---------------- scratch (device globals) -----------------------------------
__device__ __nv_bfloat16 g_a2[(size_t)NODES_P * KPA];  // ~102 MB
__device__ __nv_bfloat16 g_b2[F2 * KPB];
__device__ float g_hw[(size_t)NODES * F];              // (h@W)*norm
__device__ int   g_deg[NODES];
__device__ int   g_off[NODES];
__device__ int   g_cur[NODES];
__device__ int   g_csrc[EDGES];
__device__ int   g_bsum[128];

// ---------------- CSR build --------------------------------------------------
__global__ void k_zero_deg() {
    int i = blockIdx.x * blockDim.x + threadIdx.x;
    if (i < NODES) g_deg[i] = 0;
}

__global__ void k_count(const int* __restrict__ dst) {
    int e = blockIdx.x * blockDim.x + threadIdx.x;
    if (e < EDGES) atomicAdd(&g_deg[dst[e]], 1);
}

__global__ void k_scan1() {
    __shared__ int sm[1024];
    int i = blockIdx.x * 1024 + threadIdx.x;
    int v = (i < NODES) ? g_deg[i] : 0;
    sm[threadIdx.x] = v;
    __syncthreads();
    for (int s = 1; s < 1024; s <<= 1) {
        int t = (threadIdx.x >= s) ? sm[threadIdx.x - s] : 0;
        __syncthreads();
        sm[threadIdx.x] += t;
        __syncthreads();
    }
    if (i < NODES) g_off[i] = sm[threadIdx.x] - v;
    if (threadIdx.x == 1023) g_bsum[blockIdx.x] = sm[1023];
}

__global__ void k_scan2(int nblocks) {   // single block, 128 threads, Hillis-Steele
    __shared__ int sm[128];
    int t = threadIdx.x;
    int v = (t < nblocks) ? g_bsum[t] : 0;
    sm[t] = v;
    __syncthreads();
#pragma unroll
    for (int s = 1; s < 128; s <<= 1) {
        int u = (t >= s) ? sm[t - s] : 0;
        __syncthreads();
        sm[t] += u;
        __syncthreads();
    }
    if (t < nblocks) g_bsum[t] = sm[t] - v;   // exclusive
}

__global__ void k_scan3() {
    int i = blockIdx.x * blockDim.x + threadIdx.x;
    if (i < NODES) {
        int o = g_off[i] + g_bsum[i >> 10];
        g_off[i] = o;
        g_cur[i] = o;
    }
}

__global__ void k_scatter(const int* __restrict__ src, const int* __restrict__ dst) {
    int e = blockIdx.x * blockDim.x + threadIdx.x;
    if (e < EDGES) {
        int p = atomicAdd(&g_cur[dst[e]], 1);
        g_csrc[p] = src[e];
    }
}

// ---------------- fp32 -> bf16 hi/lo operand build ---------------------------
__global__ void k_conv_h(const float* __restrict__ h) {
    int i = blockIdx.x * blockDim.x + threadIdx.x;   // over NODES_P*64 float4s
    if (i >= NODES_P * (F / 4)) return;
    int row = i >> 6;
    int c4  = (i & 63) * 4;
    float4 v = make_float4(0.f, 0.f, 0.f, 0.f);
    if (row < NODES) v = *(const float4*)&h[(size_t)row * F + c4];
    __nv_bfloat16 hi[4], lo[4];
    float x[4] = {v.x, v.y, v.z, v.w};
#pragma unroll
    for (int j = 0; j < 4; j++) {
        hi[j] = __float2bfloat16_rn(x[j]);
        lo[j] = __float2bfloat16_rn(x[j] - __bfloat162float(hi[j]));
    }
    size_t o = (size_t)row * KPA;
    *(uint2*)&g_a2[o + c4]     = *(uint2*)hi;
    *(uint2*)&g_a2[o + F + c4] = *(uint2*)lo;
}

// B' [n][k'] K-major: n<256 -> weight[k][n]; n>=256 -> res_w[n-256][k]
__global__ void k_conv_b(const float* __restrict__ weight, const float* __restrict__ res_w) {
    int i = blockIdx.x * blockDim.x + threadIdx.x;   // over F2*F
    if (i >= F2 * F) return;
    int n = i / F, k = i % F;
    float x = (n < F) ? weight[k * F + n] : res_w[(n - F) * F + k];
    __nv_bfloat16 hi = __float2bfloat16_rn(x);
    __nv_bfloat16 lo = __float2bfloat16_rn(x - __bfloat162float(hi));
    size_t o = (size_t)n * KPB;
    g_b2[o + k]         = hi;
    g_b2[o + F + k]     = hi;
    g_b2[o + 2 * F + k] = lo;
}

// ---------------- HMMA GEMM (mma.sync m16n8k16 bf16) --------------------------
#define BM 128
#define BN 128
#define BK 64
#define NKC (KPB / BK)            // 12 chunks; A chunks 8..11 remap to hi (0..3)
#define SMEM_DYN (4 * 16384)

__device__ __forceinline__ uint32_t smem_u32(const void* p) {
    uint32_t a;
    asm("{ .reg .u64 t; cvta.to.shared.u64 t, %1; cvt.u32.u64 %0, t; }" : "=r"(a) : "l"(p));
    return a;
}

__device__ __forceinline__ int aoff(int kc) { return (kc < 8 ? kc : kc - 8) * BK; }

// 128B-row swizzle: 16B chunk cg within row r goes to cg ^ (r&7)
__device__ __forceinline__ uint32_t sw(uint32_t r, uint32_t cg) {
    return r * 128u + ((cg ^ (r & 7u)) << 4);
}

__device__ __forceinline__ void cp16(uint32_t s, const void* g) {
    asm volatile("cp.async.cg.shared.global [%0], [%1], 16;" :: "r"(s), "l"(g));
}

__device__ __forceinline__ void ldsm_x4(uint32_t* r, uint32_t addr) {
    asm volatile("ldmatrix.sync.aligned.m8n8.x4.shared.b16 {%0,%1,%2,%3}, [%4];"
                 : "=r"(r[0]), "=r"(r[1]), "=r"(r[2]), "=r"(r[3]) : "r"(addr));
}

__device__ __forceinline__ void mma_bf16(float* d, const uint32_t* a, uint32_t b0, uint32_t b1) {
    asm volatile(
        "mma.sync.aligned.m16n8k16.row.col.f32.bf16.bf16.f32 "
        "{%0,%1,%2,%3}, {%4,%5,%6,%7}, {%8,%9}, {%0,%1,%2,%3};"
        : "+f"(d[0]), "+f"(d[1]), "+f"(d[2]), "+f"(d[3])
        : "r"(a[0]), "r"(a[1]), "r"(a[2]), "r"(a[3]), "r"(b0), "r"(b1));
}

__global__ void __launch_bounds__(256, 2) k_gemm_mma(
    const float* __restrict__ norm, const float* __restrict__ res_b,
    float* __restrict__ out)
{
    extern __shared__ char smem[];
    const int tid  = threadIdx.x;
    const int wid  = tid >> 5;
    const int lane = tid & 31;
    const int wm = wid & 1;          // 2 warps along M
    const int wn = wid >> 1;         // 4 warps along N
    const size_t m0 = (size_t)blockIdx.y * BM;
    const int n0 = blockIdx.x * BN;

    const uint32_t sbase = smem_u32(smem);

    float acc[4][4][4];
#pragma unroll
    for (int i = 0; i < 4; i++)
#pragma unroll
        for (int j = 0; j < 4; j++)
#pragma unroll
            for (int q = 0; q < 4; q++) acc[i][j][q] = 0.f;

    const __nv_bfloat16* gA = g_a2 + m0 * KPA;
    const __nv_bfloat16* gB = g_b2 + (size_t)n0 * KPB;

    const int lr = tid >> 3;   // 0..31
    const int lc = tid & 7;    // 16B chunk 0..7

    // ---- prologue: chunk 0 into buffer 0 ----
    {
        uint32_t sA = sbase, sB = sbase + 16384;
        const __nv_bfloat16* pa = gA + aoff(0) + lc * 8;
        const __nv_bfloat16* pb = gB + lc * 8;
#pragma unroll
        for (int i = 0; i < 4; i++) {
            int r = lr + i * 32;
            cp16(sA + sw(r, lc), pa + (size_t)r * KPA);
            cp16(sB + sw(r, lc), pb + (size_t)r * KPB);
        }
        asm volatile("cp.async.commit_group;");
    }

    for (int kc = 0; kc < NKC; kc++) {
        int b = kc & 1;
        if (kc + 1 < NKC) {
            uint32_t sA = sbase + (b ^ 1) * 32768, sB = sA + 16384;
            const __nv_bfloat16* pa = gA + aoff(kc + 1) + lc * 8;
            const __nv_bfloat16* pb = gB + (kc + 1) * BK + lc * 8;
#pragma unroll
            for (int i = 0; i < 4; i++) {
                int r = lr + i * 32;
                cp16(sA + sw(r, lc), pa + (size_t)r * KPA);
                cp16(sB + sw(r, lc), pb + (size_t)r * KPB);
            }
            asm volatile("cp.async.commit_group;");
            asm volatile("cp.async.wait_group 1;");
        } else {
            asm volatile("cp.async.wait_group 0;");
        }
        __syncthreads();

        uint32_t sA = sbase + b * 32768, sB = sA + 16384;
#pragma unroll
        for (int ks = 0; ks < 4; ks++) {
            uint32_t a[4][4], bb[2][4];
            {
                int row = wm * 64 + (lane & 7) + ((lane >> 3) & 1) * 8;
                int cg  = ks * 2 + (lane >> 4);
#pragma unroll
                for (int i = 0; i < 4; i++)
                    ldsm_x4(a[i], sA + sw(row + i * 16, cg));
            }
            {
                int row = wn * 32 + (lane & 7) + ((lane >> 4) & 1) * 8;
                int cg  = ks * 2 + ((lane >> 3) & 1);
#pragma unroll
                for (int j = 0; j < 2; j++)
                    ldsm_x4(bb[j], sB + sw(row + j * 16, cg));
            }
#pragma unroll
            for (int i = 0; i < 4; i++)
#pragma unroll
                for (int j = 0; j < 4; j++)
                    mma_bf16(acc[i][j], a[i], bb[j >> 1][(j & 1) * 2], bb[j >> 1][(j & 1) * 2 + 1]);
        }
        __syncthreads();
    }

    // ---- fused epilogue ----
    const int tq = lane >> 2;
    const int tr = lane & 3;
#pragma unroll
    for (int i = 0; i < 4; i++) {
        size_t row = m0 + wm * 64 + i * 16 + tq;
        bool v0 = row < NODES;
        bool v1 = (row + 8) < NODES;
        float nr0 = v0 ? norm[row] : 0.f;
        float nr1 = v1 ? norm[row + 8] : 0.f;
#pragma unroll
        for (int j = 0; j < 4; j++) {
            int cn = n0 + wn * 32 + j * 8 + tr * 2;
            if (cn < F) {
                if (v0) *(float2*)&g_hw[row * F + cn] =
                    make_float2(acc[i][j][0] * nr0, acc[i][j][1] * nr0);
                if (v1) *(float2*)&g_hw[(row + 8) * F + cn] =
                    make_float2(acc[i][j][2] * nr1, acc[i][j][3] * nr1);
            } else {
                int oc = cn - F;
                float2 rb = *(const float2*)&res_b[oc];
                if (v0) *(float2*)&out[row * F + oc] =
                    make_float2(acc[i][j][0] + rb.x, acc[i][j][1] + rb.y);
                if (v1) *(float2*)&out[(row + 8) * F + oc] =
                    make_float2(acc[i][j][2] + rb.x, acc[i][j][3] + rb.y);
            }
        }
    }
}

// ---------------- aggregation + fused epilogue -------------------------------
// One warp per node, 8 floats/lane. Unroll x4 over edges for MLP.
__global__ void __launch_bounds__(256) k_agg(
    const float* __restrict__ norm, const float* __restrict__ bias,
    float* __restrict__ out)
{
    int gw   = (blockIdx.x * blockDim.x + threadIdx.x) >> 5;
    int lane = threadIdx.x & 31;
    if (gw >= NODES) return;

    const int start = g_off[gw];
    const int deg   = g_deg[gw];
    const int fo    = lane * 8;

    float4 a0 = make_float4(0.f, 0.f, 0.f, 0.f);
    float4 a1 = make_float4(0.f, 0.f, 0.f, 0.f);

    int i = 0;
    for (; i + 4 <= deg; i += 4) {
        int s0 = g_csrc[start + i];
        int s1 = g_csrc[start + i + 1];
        int s2 = g_csrc[start + i + 2];
        int s3 = g_csrc[start + i + 3];
        const float4* p0 = (const float4*)&g_hw[(size_t)s0 * F + fo];
        const float4* p1 = (const float4*)&g_hw[(size_t)s1 * F + fo];
        const float4* p2 = (const float4*)&g_hw[(size_t)s2 * F + fo];
        const float4* p3 = (const float4*)&g_hw[(size_t)s3 * F + fo];
        float4 v00 = p0[0], v01 = p0[1];
        float4 v10 = p1[0], v11 = p1[1];
        float4 v20 = p2[0], v21 = p2[1];
        float4 v30 = p3[0], v31 = p3[1];
        a0.x += v00.x; a0.y += v00.y; a0.z += v00.z; a0.w += v00.w;
        a1.x += v01.x; a1.y += v01.y; a1.z += v01.z; a1.w += v01.w;
        a0.x += v10.x; a0.y += v10.y; a0.z += v10.z; a0.w += v10.w;
        a1.x += v11.x; a1.y += v11.y; a1.z += v11.z; a1.w += v11.w;
        a0.x += v20.x; a0.y += v20.y; a0.z += v20.z; a0.w += v20.w;
        a1.x += v21.x; a1.y += v21.y; a1.z += v21.z; a1.w += v21.w;
        a0.x += v30.x; a0.y += v30.y; a0.z += v30.z; a0.w += v30.w;
        a1.x += v31.x; a1.y += v31.y; a1.z += v31.z; a1.w += v31.w;
    }
    for (; i < deg; i++) {
        int s = g_csrc[start + i];
        const float4* p = (const float4*)&g_hw[(size_t)s * F + fo];
        float4 v0 = p[0];
        float4 v1 = p[1];
        a0.x += v0.x; a0.y += v0.y; a0.z += v0.z; a0.w += v0.w;
        a1.x += v1.x; a1.y += v1.y; a1.z += v1.z; a1.w += v1.w;
    }

    float nr = norm[gw];
    float4 b0 = *(const float4*)&bias[fo];
    float4 b1 = *(const float4*)&bias[fo + 4];
    float4 r0 = *(const float4*)&out[(size_t)gw * F + fo];
    float4 r1 = *(const float4*)&out[(size_t)gw * F + fo + 4];

    float4 o0, o1;
    o0.x = fmaxf(a0.x * nr + b0.x + r0.x, 0.f);
    o0.y = fmaxf(a0.y * nr + b0.y + r0.y, 0.f);
    o0.z = fmaxf(a0.z * nr + b0.z + r0.z, 0.f);
    o0.w = fmaxf(a0.w * nr + b0.w + r0.w, 0.f);
    o1.x = fmaxf(a1.x * nr + b1.x + r1.x, 0.f);
    o1.y = fmaxf(a1.y * nr + b1.y + r1.y, 0.f);
    o1.z = fmaxf(a1.z * nr + b1.z + r1.z, 0.f);
    o1.w = fmaxf(a1.w * nr + b1.w + r1.w, 0.f);

    *(float4*)&out[(size_t)gw * F + fo]     = o0;
    *(float4*)&out[(size_t)gw * F + fo + 4] = o1;
}

// ---------------- launch ------------------------------------------------------
extern "C" void kernel_launch(void* const* d_in, const int* in_sizes, int n_in,
                              void* d_out, int out_size)
{
    const float* h      = (const float*)d_in[0];
    const float* norm   = (const float*)d_in[1];
    const int*   src    = (const int*)d_in[2];
    const int*   dst    = (const int*)d_in[3];
    const float* weight = (const float*)d_in[4];
    const float* bias   = (const float*)d_in[5];
    const float* res_w  = (const float*)d_in[6];
    const float* res_b  = (const float*)d_in[7];
    float* out = (float*)d_out;

    (void)in_sizes; (void)n_in; (void)out_size;

    cudaFuncSetAttribute(k_gemm_mma, cudaFuncAttributeMaxDynamicSharedMemorySize, SMEM_DYN);

    // CSR build
    k_zero_deg<<<(NODES + 255) / 256, 256>>>();
    k_count<<<(EDGES + 255) / 256, 256>>>(dst);
    int nscan = (NODES + 1023) / 1024;
    k_scan1<<<nscan, 1024>>>();
    k_scan2<<<1, 128>>>(nscan);
    k_scan3<<<(NODES + 255) / 256, 256>>>();
    k_scatter<<<(EDGES + 255) / 256, 256>>>(src, dst);

    // bf16 hi/lo operand build
    k_conv_h<<<(NODES_P * (F / 4) + 255) / 256, 256>>>(h);
    k_conv_b<<<(F2 * F + 255) / 256, 256>>>(weight, res_w);

    // HMMA dual GEMM: hw -> g_hw, res -> out
    dim3 ggrid(F2 / BN, NODES_P / BM);   // 4 x 782
    k_gemm_mma<<<ggrid, 256, SMEM_DYN>>>(norm, res_b, out);

    // aggregation + epilogue
    int nwarp_blocks = (NODES * 32 + 255) / 256;
    k_agg<<<nwarp_blocks, 256>>>(norm, bias, out);
}

// round 5
// speedup vs baseline: 2.2772x; 1.1637x over previous
#include <cuda_runtime.h>
#include <cuda_bf16.h>
#include <cuda_fp16.h>
#include <cstdint>

#define NODES 100000
#define NODES_P 100096            // 782 * 128
#define EDGES 1600000
#define F 256
#define F2 512
#define KPA 512                   // A' = [Ahi | Alo]
#define KPB 768                   // B' = [Bhi ; Bhi ; Blo]

// ---------------- scratch (device globals) -----------------------------------
__device__ __nv_bfloat16 g_a2[(size_t)NODES_P * KPA];  // ~102 MB
__device__ __nv_bfloat16 g_b2[F2 * KPB];
__device__ __half g_hw[(size_t)NODES * F];             // (h@W)*norm, fp16: 51 MB (fits L2)
__device__ int   g_deg[NODES];
__device__ int   g_off[NODES];
__device__ int   g_cur[NODES];
__device__ int   g_csrc[EDGES];
__device__ int   g_bsum[128];

// ---------------- CSR build --------------------------------------------------
__global__ void k_zero_deg() {
    int i = blockIdx.x * blockDim.x + threadIdx.x;
    if (i < NODES) g_deg[i] = 0;
}

__global__ void k_count(const int* __restrict__ dst) {
    int e = blockIdx.x * blockDim.x + threadIdx.x;
    if (e < EDGES) atomicAdd(&g_deg[dst[e]], 1);
}

__global__ void k_scan1() {
    __shared__ int sm[1024];
    int i = blockIdx.x * 1024 + threadIdx.x;
    int v = (i < NODES) ? g_deg[i] : 0;
    sm[threadIdx.x] = v;
    __syncthreads();
    for (int s = 1; s < 1024; s <<= 1) {
        int t = (threadIdx.x >= s) ? sm[threadIdx.x - s] : 0;
        __syncthreads();
        sm[threadIdx.x] += t;
        __syncthreads();
    }
    if (i < NODES) g_off[i] = sm[threadIdx.x] - v;
    if (threadIdx.x == 1023) g_bsum[blockIdx.x] = sm[1023];
}

__global__ void k_scan2(int nblocks) {
    __shared__ int sm[128];
    int t = threadIdx.x;
    int v = (t < nblocks) ? g_bsum[t] : 0;
    sm[t] = v;
    __syncthreads();
#pragma unroll
    for (int s = 1; s < 128; s <<= 1) {
        int u = (t >= s) ? sm[t - s] : 0;
        __syncthreads();
        sm[t] += u;
        __syncthreads();
    }
    if (t < nblocks) g_bsum[t] = sm[t] - v;   // exclusive
}

__global__ void k_scan3() {
    int i = blockIdx.x * blockDim.x + threadIdx.x;
    if (i < NODES) {
        int o = g_off[i] + g_bsum[i >> 10];
        g_off[i] = o;
        g_cur[i] = o;
    }
}

__global__ void k_scatter(const int* __restrict__ src, const int* __restrict__ dst) {
    int e = blockIdx.x * blockDim.x + threadIdx.x;
    if (e < EDGES) {
        int p = atomicAdd(&g_cur[dst[e]], 1);
        g_csrc[p] = src[e];
    }
}

// ---------------- fp32 -> bf16 hi/lo operand build ---------------------------
__global__ void k_conv_h(const float* __restrict__ h) {
    int i = blockIdx.x * blockDim.x + threadIdx.x;
    if (i >= NODES_P * (F / 4)) return;
    int row = i >> 6;
    int c4  = (i & 63) * 4;
    float4 v = make_float4(0.f, 0.f, 0.f, 0.f);
    if (row < NODES) v = *(const float4*)&h[(size_t)row * F + c4];
    __nv_bfloat16 hi[4], lo[4];
    float x[4] = {v.x, v.y, v.z, v.w};
#pragma unroll
    for (int j = 0; j < 4; j++) {
        hi[j] = __float2bfloat16_rn(x[j]);
        lo[j] = __float2bfloat16_rn(x[j] - __bfloat162float(hi[j]));
    }
    size_t o = (size_t)row * KPA;
    *(uint2*)&g_a2[o + c4]     = *(uint2*)hi;
    *(uint2*)&g_a2[o + F + c4] = *(uint2*)lo;
}

// B' [n][k'] K-major: n<256 -> weight[k][n]; n>=256 -> res_w[n-256][k]
__global__ void k_conv_b(const float* __restrict__ weight, const float* __restrict__ res_w) {
    int i = blockIdx.x * blockDim.x + threadIdx.x;
    if (i >= F2 * F) return;
    int n = i / F, k = i % F;
    float x = (n < F) ? weight[k * F + n] : res_w[(n - F) * F + k];
    __nv_bfloat16 hi = __float2bfloat16_rn(x);
    __nv_bfloat16 lo = __float2bfloat16_rn(x - __bfloat162float(hi));
    size_t o = (size_t)n * KPB;
    g_b2[o + k]         = hi;
    g_b2[o + F + k]     = hi;
    g_b2[o + 2 * F + k] = lo;
}

// ---------------- HMMA GEMM (mma.sync m16n8k16 bf16) --------------------------
#define BM 128
#define BN 128
#define BK 64
#define NKC (KPB / BK)            // 12 chunks; A chunks 8..11 remap to hi (0..3)
#define SMEM_DYN (4 * 16384)

__device__ __forceinline__ uint32_t smem_u32(const void* p) {
    uint32_t a;
    asm("{ .reg .u64 t; cvta.to.shared.u64 t, %1; cvt.u32.u64 %0, t; }" : "=r"(a) : "l"(p));
    return a;
}

__device__ __forceinline__ int aoff(int kc) { return (kc < 8 ? kc : kc - 8) * BK; }

__device__ __forceinline__ uint32_t sw(uint32_t r, uint32_t cg) {
    return r * 128u + ((cg ^ (r & 7u)) << 4);
}

__device__ __forceinline__ void cp16(uint32_t s, const void* g) {
    asm volatile("cp.async.cg.shared.global [%0], [%1], 16;" :: "r"(s), "l"(g));
}

__device__ __forceinline__ void ldsm_x4(uint32_t* r, uint32_t addr) {
    asm volatile("ldmatrix.sync.aligned.m8n8.x4.shared.b16 {%0,%1,%2,%3}, [%4];"
                 : "=r"(r[0]), "=r"(r[1]), "=r"(r[2]), "=r"(r[3]) : "r"(addr));
}

__device__ __forceinline__ void mma_bf16(float* d, const uint32_t* a, uint32_t b0, uint32_t b1) {
    asm volatile(
        "mma.sync.aligned.m16n8k16.row.col.f32.bf16.bf16.f32 "
        "{%0,%1,%2,%3}, {%4,%5,%6,%7}, {%8,%9}, {%0,%1,%2,%3};"
        : "+f"(d[0]), "+f"(d[1]), "+f"(d[2]), "+f"(d[3])
        : "r"(a[0]), "r"(a[1]), "r"(a[2]), "r"(a[3]), "r"(b0), "r"(b1));
}

__global__ void __launch_bounds__(256, 2) k_gemm_mma(
    const float* __restrict__ norm, const float* __restrict__ res_b,
    float* __restrict__ out)
{
    extern __shared__ char smem[];
    const int tid  = threadIdx.x;
    const int wid  = tid >> 5;
    const int lane = tid & 31;
    const int wm = wid & 1;
    const int wn = wid >> 1;
    const size_t m0 = (size_t)blockIdx.y * BM;
    const int n0 = blockIdx.x * BN;

    const uint32_t sbase = smem_u32(smem);

    float acc[4][4][4];
#pragma unroll
    for (int i = 0; i < 4; i++)
#pragma unroll
        for (int j = 0; j < 4; j++)
#pragma unroll
            for (int q = 0; q < 4; q++) acc[i][j][q] = 0.f;

    const __nv_bfloat16* gA = g_a2 + m0 * KPA;
    const __nv_bfloat16* gB = g_b2 + (size_t)n0 * KPB;

    const int lr = tid >> 3;
    const int lc = tid & 7;

    {
        uint32_t sA = sbase, sB = sbase + 16384;
        const __nv_bfloat16* pa = gA + aoff(0) + lc * 8;
        const __nv_bfloat16* pb = gB + lc * 8;
#pragma unroll
        for (int i = 0; i < 4; i++) {
            int r = lr + i * 32;
            cp16(sA + sw(r, lc), pa + (size_t)r * KPA);
            cp16(sB + sw(r, lc), pb + (size_t)r * KPB);
        }
        asm volatile("cp.async.commit_group;");
    }

    for (int kc = 0; kc < NKC; kc++) {
        int b = kc & 1;
        if (kc + 1 < NKC) {
            uint32_t sA = sbase + (b ^ 1) * 32768, sB = sA + 16384;
            const __nv_bfloat16* pa = gA + aoff(kc + 1) + lc * 8;
            const __nv_bfloat16* pb = gB + (kc + 1) * BK + lc * 8;
#pragma unroll
            for (int i = 0; i < 4; i++) {
                int r = lr + i * 32;
                cp16(sA + sw(r, lc), pa + (size_t)r * KPA);
                cp16(sB + sw(r, lc), pb + (size_t)r * KPB);
            }
            asm volatile("cp.async.commit_group;");
            asm volatile("cp.async.wait_group 1;");
        } else {
            asm volatile("cp.async.wait_group 0;");
        }
        __syncthreads();

        uint32_t sA = sbase + b * 32768, sB = sA + 16384;
#pragma unroll
        for (int ks = 0; ks < 4; ks++) {
            uint32_t a[4][4], bb[2][4];
            {
                int row = wm * 64 + (lane & 7) + ((lane >> 3) & 1) * 8;
                int cg  = ks * 2 + (lane >> 4);
#pragma unroll
                for (int i = 0; i < 4; i++)
                    ldsm_x4(a[i], sA + sw(row + i * 16, cg));
            }
            {
                int row = wn * 32 + (lane & 7) + ((lane >> 4) & 1) * 8;
                int cg  = ks * 2 + ((lane >> 3) & 1);
#pragma unroll
                for (int j = 0; j < 2; j++)
                    ldsm_x4(bb[j], sB + sw(row + j * 16, cg));
            }
#pragma unroll
            for (int i = 0; i < 4; i++)
#pragma unroll
                for (int j = 0; j < 4; j++)
                    mma_bf16(acc[i][j], a[i], bb[j >> 1][(j & 1) * 2], bb[j >> 1][(j & 1) * 2 + 1]);
        }
        __syncthreads();
    }

    // ---- fused epilogue: W half -> g_hw (fp16), residual half -> out (fp32) ----
    const int tq = lane >> 2;
    const int tr = lane & 3;
#pragma unroll
    for (int i = 0; i < 4; i++) {
        size_t row = m0 + wm * 64 + i * 16 + tq;
        bool v0 = row < NODES;
        bool v1 = (row + 8) < NODES;
        float nr0 = v0 ? norm[row] : 0.f;
        float nr1 = v1 ? norm[row + 8] : 0.f;
#pragma unroll
        for (int j = 0; j < 4; j++) {
            int cn = n0 + wn * 32 + j * 8 + tr * 2;
            if (cn < F) {
                if (v0) *(__half2*)&g_hw[row * F + cn] =
                    __floats2half2_rn(acc[i][j][0] * nr0, acc[i][j][1] * nr0);
                if (v1) *(__half2*)&g_hw[(row + 8) * F + cn] =
                    __floats2half2_rn(acc[i][j][2] * nr1, acc[i][j][3] * nr1);
            } else {
                int oc = cn - F;
                float2 rb = *(const float2*)&res_b[oc];
                if (v0) *(float2*)&out[row * F + oc] =
                    make_float2(acc[i][j][0] + rb.x, acc[i][j][1] + rb.y);
                if (v1) *(float2*)&out[(row + 8) * F + oc] =
                    make_float2(acc[i][j][2] + rb.x, acc[i][j][3] + rb.y);
            }
        }
    }
}

// ---------------- aggregation + fused epilogue -------------------------------
// One warp per node, 8 fp16 feats/lane (one uint4 per edge). Unroll x8 for MLP.
__device__ __forceinline__ void acc8(float* a, uint4 v) {
    float2 f0 = __half22float2(*(__half2*)&v.x);
    float2 f1 = __half22float2(*(__half2*)&v.y);
    float2 f2 = __half22float2(*(__half2*)&v.z);
    float2 f3 = __half22float2(*(__half2*)&v.w);
    a[0] += f0.x; a[1] += f0.y; a[2] += f1.x; a[3] += f1.y;
    a[4] += f2.x; a[5] += f2.y; a[6] += f3.x; a[7] += f3.y;
}

__global__ void __launch_bounds__(256) k_agg(
    const float* __restrict__ norm, const float* __restrict__ bias,
    float* __restrict__ out)
{
    int gw   = (blockIdx.x * blockDim.x + threadIdx.x) >> 5;
    int lane = threadIdx.x & 31;
    if (gw >= NODES) return;

    const int start = g_off[gw];
    const int deg   = g_deg[gw];
    const int fo    = lane * 8;

    float a[8];
#pragma unroll
    for (int q = 0; q < 8; q++) a[q] = 0.f;

    int i = 0;
    for (; i + 8 <= deg; i += 8) {
        int s[8];
#pragma unroll
        for (int u = 0; u < 8; u++) s[u] = g_csrc[start + i + u];
        uint4 v[8];
#pragma unroll
        for (int u = 0; u < 8; u++)
            v[u] = *(const uint4*)&g_hw[(size_t)s[u] * F + fo];
#pragma unroll
        for (int u = 0; u < 8; u++) acc8(a, v[u]);
    }
    for (; i + 2 <= deg; i += 2) {
        int s0 = g_csrc[start + i];
        int s1 = g_csrc[start + i + 1];
        uint4 v0 = *(const uint4*)&g_hw[(size_t)s0 * F + fo];
        uint4 v1 = *(const uint4*)&g_hw[(size_t)s1 * F + fo];
        acc8(a, v0);
        acc8(a, v1);
    }
    if (i < deg) {
        int s = g_csrc[start + i];
        acc8(a, *(const uint4*)&g_hw[(size_t)s * F + fo]);
    }

    float nr = norm[gw];
    float4 b0 = *(const float4*)&bias[fo];
    float4 b1 = *(const float4*)&bias[fo + 4];
    float4 r0 = *(const float4*)&out[(size_t)gw * F + fo];
    float4 r1 = *(const float4*)&out[(size_t)gw * F + fo + 4];

    float4 o0, o1;
    o0.x = fmaxf(a[0] * nr + b0.x + r0.x, 0.f);
    o0.y = fmaxf(a[1] * nr + b0.y + r0.y, 0.f);
    o0.z = fmaxf(a[2] * nr + b0.z + r0.z, 0.f);
    o0.w = fmaxf(a[3] * nr + b0.w + r0.w, 0.f);
    o1.x = fmaxf(a[4] * nr + b1.x + r1.x, 0.f);
    o1.y = fmaxf(a[5] * nr + b1.y + r1.y, 0.f);
    o1.z = fmaxf(a[6] * nr + b1.z + r1.z, 0.f);
    o1.w = fmaxf(a[7] * nr + b1.w + r1.w, 0.f);

    *(float4*)&out[(size_t)gw * F + fo]     = o0;
    *(float4*)&out[(size_t)gw * F + fo + 4] = o1;
}

// ---------------- launch ------------------------------------------------------
extern "C" void kernel_launch(void* const* d_in, const int* in_sizes, int n_in,
                              void* d_out, int out_size)
{
    const float* h      = (const float*)d_in[0];
    const float* norm   = (const float*)d_in[1];
    const int*   src    = (const int*)d_in[2];
    const int*   dst    = (const int*)d_in[3];
    const float* weight = (const float*)d_in[4];
    const float* bias   = (const float*)d_in[5];
    const float* res_w  = (const float*)d_in[6];
    const float* res_b  = (const float*)d_in[7];
    float* out = (float*)d_out;

    (void)in_sizes; (void)n_in; (void)out_size;

    cudaFuncSetAttribute(k_gemm_mma, cudaFuncAttributeMaxDynamicSharedMemorySize, SMEM_DYN);

    // CSR build
    k_zero_deg<<<(NODES + 255) / 256, 256>>>();
    k_count<<<(EDGES + 255) / 256, 256>>>(dst);
    int nscan = (NODES + 1023) / 1024;
    k_scan1<<<nscan, 1024>>>();
    k_scan2<<<1, 128>>>(nscan);
    k_scan3<<<(NODES + 255) / 256, 256>>>();
    k_scatter<<<(EDGES + 255) / 256, 256>>>(src, dst);

    // bf16 hi/lo operand build
    k_conv_h<<<(NODES_P * (F / 4) + 255) / 256, 256>>>(h);
    k_conv_b<<<(F2 * F + 255) / 256, 256>>>(weight, res_w);

    // HMMA dual GEMM: hw -> g_hw (fp16), res -> out
    dim3 ggrid(F2 / BN, NODES_P / BM);
    k_gemm_mma<<<ggrid, 256, SMEM_DYN>>>(norm, res_b, out);

    // aggregation + epilogue
    int nwarp_blocks = (NODES * 32 + 255) / 256;
    k_agg<<<nwarp_blocks, 256>>>(norm, bias, out);
}

// round 6
// speedup vs baseline: 3.3338x; 1.4640x over previous
#include <cuda_runtime.h>
#include <cuda_fp16.h>
#include <cstdint>

#define NODES 100000
#define NODES_P 100096            // 782 * 128
#define EDGES 1600000
#define F 256
#define F2 512

// ---------------- scratch (device globals) -----------------------------------
__device__ __half g_a2[(size_t)NODES_P * F];   // h in fp16, 51 MB
__device__ __half g_b2[F2 * F];                // combined weight [n][k] fp16, 256 KB
__device__ __half g_hw[(size_t)NODES * F];     // (h@W)*norm fp16, 51 MB (fits L2)
__device__ int   g_deg[NODES];
__device__ int   g_off[NODES];
__device__ int   g_cur[NODES];
__device__ int   g_csrc[EDGES];
__device__ int   g_bsum[128];

// ---------------- CSR build --------------------------------------------------
__global__ void k_zero_deg() {
    int i = blockIdx.x * blockDim.x + threadIdx.x;
    if (i < NODES) g_deg[i] = 0;
}

__global__ void k_count(const int* __restrict__ dst) {
    int e = blockIdx.x * blockDim.x + threadIdx.x;
    if (e < EDGES) atomicAdd(&g_deg[dst[e]], 1);
}

__global__ void k_scan1() {
    __shared__ int sm[1024];
    int i = blockIdx.x * 1024 + threadIdx.x;
    int v = (i < NODES) ? g_deg[i] : 0;
    sm[threadIdx.x] = v;
    __syncthreads();
    for (int s = 1; s < 1024; s <<= 1) {
        int t = (threadIdx.x >= s) ? sm[threadIdx.x - s] : 0;
        __syncthreads();
        sm[threadIdx.x] += t;
        __syncthreads();
    }
    if (i < NODES) g_off[i] = sm[threadIdx.x] - v;
    if (threadIdx.x == 1023) g_bsum[blockIdx.x] = sm[1023];
}

__global__ void k_scan2(int nblocks) {
    __shared__ int sm[128];
    int t = threadIdx.x;
    int v = (t < nblocks) ? g_bsum[t] : 0;
    sm[t] = v;
    __syncthreads();
#pragma unroll
    for (int s = 1; s < 128; s <<= 1) {
        int u = (t >= s) ? sm[t - s] : 0;
        __syncthreads();
        sm[t] += u;
        __syncthreads();
    }
    if (t < nblocks) g_bsum[t] = sm[t] - v;   // exclusive
}

__global__ void k_scan3() {
    int i = blockIdx.x * blockDim.x + threadIdx.x;
    if (i < NODES) {
        int o = g_off[i] + g_bsum[i >> 10];
        g_off[i] = o;
        g_cur[i] = o;
    }
}

__global__ void k_scatter(const int* __restrict__ src, const int* __restrict__ dst) {
    int e = blockIdx.x * blockDim.x + threadIdx.x;
    if (e < EDGES) {
        int p = atomicAdd(&g_cur[dst[e]], 1);
        g_csrc[p] = src[e];
    }
}

// ---------------- fp32 -> fp16 operand build ----------------------------------
__global__ void k_conv_h(const float* __restrict__ h) {
    int i = blockIdx.x * blockDim.x + threadIdx.x;   // over NODES_P*64 float4s
    if (i >= NODES_P * (F / 4)) return;
    int row = i >> 6;
    int c4  = (i & 63) * 4;
    float4 v = make_float4(0.f, 0.f, 0.f, 0.f);
    if (row < NODES) v = *(const float4*)&h[(size_t)row * F + c4];
    __half2 p0 = __floats2half2_rn(v.x, v.y);
    __half2 p1 = __floats2half2_rn(v.z, v.w);
    *(__half2*)&g_a2[(size_t)row * F + c4]     = p0;
    *(__half2*)&g_a2[(size_t)row * F + c4 + 2] = p1;
}

// B [n][k] K-major: n<256 -> weight[k][n]; n>=256 -> res_w[n-256][k]
__global__ void k_conv_b(const float* __restrict__ weight, const float* __restrict__ res_w) {
    int i = blockIdx.x * blockDim.x + threadIdx.x;   // over F2*F
    if (i >= F2 * F) return;
    int n = i / F, k = i % F;
    float x = (n < F) ? weight[k * F + n] : res_w[(n - F) * F + k];
    g_b2[i] = __float2half_rn(x);
}

// ---------------- HMMA GEMM (mma.sync m16n8k16 fp16) --------------------------
#define BM 128
#define BN 128
#define BK 64
#define NKC (F / BK)              // 4
#define SMEM_DYN (4 * 16384)

__device__ __forceinline__ uint32_t smem_u32(const void* p) {
    uint32_t a;
    asm("{ .reg .u64 t; cvta.to.shared.u64 t, %1; cvt.u32.u64 %0, t; }" : "=r"(a) : "l"(p));
    return a;
}

__device__ __forceinline__ uint32_t sw(uint32_t r, uint32_t cg) {
    return r * 128u + ((cg ^ (r & 7u)) << 4);
}

__device__ __forceinline__ void cp16(uint32_t s, const void* g) {
    asm volatile("cp.async.cg.shared.global [%0], [%1], 16;" :: "r"(s), "l"(g));
}

__device__ __forceinline__ void ldsm_x4(uint32_t* r, uint32_t addr) {
    asm volatile("ldmatrix.sync.aligned.m8n8.x4.shared.b16 {%0,%1,%2,%3}, [%4];"
                 : "=r"(r[0]), "=r"(r[1]), "=r"(r[2]), "=r"(r[3]) : "r"(addr));
}

__device__ __forceinline__ void mma_fp16(float* d, const uint32_t* a, uint32_t b0, uint32_t b1) {
    asm volatile(
        "mma.sync.aligned.m16n8k16.row.col.f32.f16.f16.f32 "
        "{%0,%1,%2,%3}, {%4,%5,%6,%7}, {%8,%9}, {%0,%1,%2,%3};"
        : "+f"(d[0]), "+f"(d[1]), "+f"(d[2]), "+f"(d[3])
        : "r"(a[0]), "r"(a[1]), "r"(a[2]), "r"(a[3]), "r"(b0), "r"(b1));
}

__global__ void __launch_bounds__(256, 2) k_gemm_mma(
    const float* __restrict__ norm, const float* __restrict__ res_b,
    float* __restrict__ out)
{
    extern __shared__ char smem[];
    const int tid  = threadIdx.x;
    const int wid  = tid >> 5;
    const int lane = tid & 31;
    const int wm = wid & 1;
    const int wn = wid >> 1;
    const size_t m0 = (size_t)blockIdx.y * BM;
    const int n0 = blockIdx.x * BN;

    const uint32_t sbase = smem_u32(smem);

    float acc[4][4][4];
#pragma unroll
    for (int i = 0; i < 4; i++)
#pragma unroll
        for (int j = 0; j < 4; j++)
#pragma unroll
            for (int q = 0; q < 4; q++) acc[i][j][q] = 0.f;

    const __half* gA = g_a2 + m0 * F;
    const __half* gB = g_b2 + (size_t)n0 * F;

    const int lr = tid >> 3;
    const int lc = tid & 7;

    {
        uint32_t sA = sbase, sB = sbase + 16384;
        const __half* pa = gA + lc * 8;
        const __half* pb = gB + lc * 8;
#pragma unroll
        for (int i = 0; i < 4; i++) {
            int r = lr + i * 32;
            cp16(sA + sw(r, lc), pa + (size_t)r * F);
            cp16(sB + sw(r, lc), pb + (size_t)r * F);
        }
        asm volatile("cp.async.commit_group;");
    }

    for (int kc = 0; kc < NKC; kc++) {
        int b = kc & 1;
        if (kc + 1 < NKC) {
            uint32_t sA = sbase + (b ^ 1) * 32768, sB = sA + 16384;
            const __half* pa = gA + (kc + 1) * BK + lc * 8;
            const __half* pb = gB + (kc + 1) * BK + lc * 8;
#pragma unroll
            for (int i = 0; i < 4; i++) {
                int r = lr + i * 32;
                cp16(sA + sw(r, lc), pa + (size_t)r * F);
                cp16(sB + sw(r, lc), pb + (size_t)r * F);
            }
            asm volatile("cp.async.commit_group;");
            asm volatile("cp.async.wait_group 1;");
        } else {
            asm volatile("cp.async.wait_group 0;");
        }
        __syncthreads();

        uint32_t sA = sbase + b * 32768, sB = sA + 16384;
#pragma unroll
        for (int ks = 0; ks < 4; ks++) {
            uint32_t a[4][4], bb[2][4];
            {
                int row = wm * 64 + (lane & 7) + ((lane >> 3) & 1) * 8;
                int cg  = ks * 2 + (lane >> 4);
#pragma unroll
                for (int i = 0; i < 4; i++)
                    ldsm_x4(a[i], sA + sw(row + i * 16, cg));
            }
            {
                int row = wn * 32 + (lane & 7) + ((lane >> 4) & 1) * 8;
                int cg  = ks * 2 + ((lane >> 3) & 1);
#pragma unroll
                for (int j = 0; j < 2; j++)
                    ldsm_x4(bb[j], sB + sw(row + j * 16, cg));
            }
#pragma unroll
            for (int i = 0; i < 4; i++)
#pragma unroll
                for (int j = 0; j < 4; j++)
                    mma_fp16(acc[i][j], a[i], bb[j >> 1][(j & 1) * 2], bb[j >> 1][(j & 1) * 2 + 1]);
        }
        __syncthreads();
    }

    // ---- fused epilogue: W half -> g_hw (fp16), residual half -> out (fp32) ----
    const int tq = lane >> 2;
    const int tr = lane & 3;
#pragma unroll
    for (int i = 0; i < 4; i++) {
        size_t row = m0 + wm * 64 + i * 16 + tq;
        bool v0 = row < NODES;
        bool v1 = (row + 8) < NODES;
        float nr0 = v0 ? norm[row] : 0.f;
        float nr1 = v1 ? norm[row + 8] : 0.f;
#pragma unroll
        for (int j = 0; j < 4; j++) {
            int cn = n0 + wn * 32 + j * 8 + tr * 2;
            if (cn < F) {
                if (v0) *(__half2*)&g_hw[row * F + cn] =
                    __floats2half2_rn(acc[i][j][0] * nr0, acc[i][j][1] * nr0);
                if (v1) *(__half2*)&g_hw[(row + 8) * F + cn] =
                    __floats2half2_rn(acc[i][j][2] * nr1, acc[i][j][3] * nr1);
            } else {
                int oc = cn - F;
                float2 rb = *(const float2*)&res_b[oc];
                if (v0) *(float2*)&out[row * F + oc] =
                    make_float2(acc[i][j][0] + rb.x, acc[i][j][1] + rb.y);
                if (v1) *(float2*)&out[(row + 8) * F + oc] =
                    make_float2(acc[i][j][2] + rb.x, acc[i][j][3] + rb.y);
            }
        }
    }
}

// ---------------- aggregation + fused epilogue -------------------------------
__device__ __forceinline__ void acc8(float* a, uint4 v) {
    float2 f0 = __half22float2(*(__half2*)&v.x);
    float2 f1 = __half22float2(*(__half2*)&v.y);
    float2 f2 = __half22float2(*(__half2*)&v.z);
    float2 f3 = __half22float2(*(__half2*)&v.w);
    a[0] += f0.x; a[1] += f0.y; a[2] += f1.x; a[3] += f1.y;
    a[4] += f2.x; a[5] += f2.y; a[6] += f3.x; a[7] += f3.y;
}

__global__ void __launch_bounds__(256) k_agg(
    const float* __restrict__ norm, const float* __restrict__ bias,
    float* __restrict__ out)
{
    int gw   = (blockIdx.x * blockDim.x + threadIdx.x) >> 5;
    int lane = threadIdx.x & 31;
    if (gw >= NODES) return;

    const int start = g_off[gw];
    const int deg   = g_deg[gw];
    const int fo    = lane * 8;

    float a[8];
#pragma unroll
    for (int q = 0; q < 8; q++) a[q] = 0.f;

    int i = 0;
    for (; i + 8 <= deg; i += 8) {
        int s[8];
#pragma unroll
        for (int u = 0; u < 8; u++) s[u] = g_csrc[start + i + u];
        uint4 v[8];
#pragma unroll
        for (int u = 0; u < 8; u++)
            v[u] = *(const uint4*)&g_hw[(size_t)s[u] * F + fo];
#pragma unroll
        for (int u = 0; u < 8; u++) acc8(a, v[u]);
    }
    for (; i + 2 <= deg; i += 2) {
        int s0 = g_csrc[start + i];
        int s1 = g_csrc[start + i + 1];
        uint4 v0 = *(const uint4*)&g_hw[(size_t)s0 * F + fo];
        uint4 v1 = *(const uint4*)&g_hw[(size_t)s1 * F + fo];
        acc8(a, v0);
        acc8(a, v1);
    }
    if (i < deg) {
        int s = g_csrc[start + i];
        acc8(a, *(const uint4*)&g_hw[(size_t)s * F + fo]);
    }

    float nr = norm[gw];
    float4 b0 = *(const float4*)&bias[fo];
    float4 b1 = *(const float4*)&bias[fo + 4];
    float4 r0 = *(const float4*)&out[(size_t)gw * F + fo];
    float4 r1 = *(const float4*)&out[(size_t)gw * F + fo + 4];

    float4 o0, o1;
    o0.x = fmaxf(a[0] * nr + b0.x + r0.x, 0.f);
    o0.y = fmaxf(a[1] * nr + b0.y + r0.y, 0.f);
    o0.z = fmaxf(a[2] * nr + b0.z + r0.z, 0.f);
    o0.w = fmaxf(a[3] * nr + b0.w + r0.w, 0.f);
    o1.x = fmaxf(a[4] * nr + b1.x + r1.x, 0.f);
    o1.y = fmaxf(a[5] * nr + b1.y + r1.y, 0.f);
    o1.z = fmaxf(a[6] * nr + b1.z + r1.z, 0.f);
    o1.w = fmaxf(a[7] * nr + b1.w + r1.w, 0.f);

    *(float4*)&out[(size_t)gw * F + fo]     = o0;
    *(float4*)&out[(size_t)gw * F + fo + 4] = o1;
}

// ---------------- launch ------------------------------------------------------
extern "C" void kernel_launch(void* const* d_in, const int* in_sizes, int n_in,
                              void* d_out, int out_size)
{
    const float* h      = (const float*)d_in[0];
    const float* norm   = (const float*)d_in[1];
    const int*   src    = (const int*)d_in[2];
    const int*   dst    = (const int*)d_in[3];
    const float* weight = (const float*)d_in[4];
    const float* bias   = (const float*)d_in[5];
    const float* res_w  = (const float*)d_in[6];
    const float* res_b  = (const float*)d_in[7];
    float* out = (float*)d_out;

    (void)in_sizes; (void)n_in; (void)out_size;

    cudaFuncSetAttribute(k_gemm_mma, cudaFuncAttributeMaxDynamicSharedMemorySize, SMEM_DYN);

    // CSR build
    k_zero_deg<<<(NODES + 255) / 256, 256>>>();
    k_count<<<(EDGES + 255) / 256, 256>>>(dst);
    int nscan = (NODES + 1023) / 1024;
    k_scan1<<<nscan, 1024>>>();
    k_scan2<<<1, 128>>>(nscan);
    k_scan3<<<(NODES + 255) / 256, 256>>>();
    k_scatter<<<(EDGES + 255) / 256, 256>>>(src, dst);

    // fp16 operand build
    k_conv_h<<<(NODES_P * (F / 4) + 255) / 256, 256>>>(h);
    k_conv_b<<<(F2 * F + 255) / 256, 256>>>(weight, res_w);

    // HMMA dual GEMM: hw -> g_hw (fp16), res -> out
    dim3 ggrid(F2 / BN, NODES_P / BM);
    k_gemm_mma<<<ggrid, 256, SMEM_DYN>>>(norm, res_b, out);

    // aggregation + epilogue
    int nwarp_blocks = (NODES * 32 + 255) / 256;
    k_agg<<<nwarp_blocks, 256>>>(norm, bias, out);
}